// round 2
// baseline (speedup 1.0000x reference)
#include <cuda_runtime.h>

// qkv scratch in windowed layout: [b(2)][wy(16)][wx(16)][ch(56)][Bs(8)][tok(64)]
#define NELEM_QKV (2*16*16*56*8*64)
__device__ float g_q[NELEM_QKV];
__device__ float g_k[NELEM_QKV];
__device__ float g_v[NELEM_QKV];

// ---------------------------------------------------------------------------
// Grouped 3x3x3 conv (56 groups, 2 in-ch / 1 out-ch per group), SAME padding.
// Thread: 4 consecutive w outputs for all 8 output depths of one (b,o,h).
// Writes windowed token layout. grid(1,16,112), block(32,8).
// ---------------------------------------------------------------------------
__global__ __launch_bounds__(256) void conv_win_kernel(
    const float* __restrict__ in, const float* __restrict__ W3, int sel)
{
  float* outw = (sel == 0) ? g_q : (sel == 1) ? g_k : g_v;
  const int z = blockIdx.z;
  const int b = z / 56, o = z % 56;
  const int h = blockIdx.y * 8 + threadIdx.y;
  const int w0 = threadIdx.x * 4;

  __shared__ float ws[54];
  const int tid = threadIdx.y * 32 + threadIdx.x;
  if (tid < 54) ws[tid] = W3[o * 54 + tid];
  __syncthreads();

  float acc[8][4];
#pragma unroll
  for (int i = 0; i < 8; i++) {
    acc[i][0] = 0.f; acc[i][1] = 0.f; acc[i][2] = 0.f; acc[i][3] = 0.f;
  }

#pragma unroll
  for (int ci = 0; ci < 2; ci++) {
    const float* basec = in + (size_t)((b * 112 + o * 2 + ci) * 8) * 16384;
#pragma unroll
    for (int dh = 0; dh < 3; dh++) {
      const int hh = h + dh - 1;
      if (hh < 0 || hh > 127) continue;
      float w9[3][3];
#pragma unroll
      for (int kd = 0; kd < 3; kd++)
#pragma unroll
        for (int dw = 0; dw < 3; dw++)
          w9[kd][dw] = ws[ci * 27 + kd * 9 + dh * 3 + dw];
      const float* rowp = basec + hh * 128 + w0;
#pragma unroll
      for (int d = 0; d < 8; d++) {          // input depth index
        const float* p = rowp + d * 16384;
        float4 m4 = *(const float4*)p;
        float v[6];
        v[0] = (w0 > 0)   ? p[-1] : 0.f;
        v[1] = m4.x; v[2] = m4.y; v[3] = m4.z; v[4] = m4.w;
        v[5] = (w0 < 124) ? p[4]  : 0.f;
#pragma unroll
        for (int kd = 0; kd < 3; kd++) {
          const int Bs = d + 1 - kd;          // output depth fed by this tap
          if (Bs < 0 || Bs > 7) continue;     // compile-time DCE
#pragma unroll
          for (int dw = 0; dw < 3; dw++) {
            const float wv = w9[kd][dw];
            acc[Bs][0] += wv * v[dw + 0];
            acc[Bs][1] += wv * v[dw + 1];
            acc[Bs][2] += wv * v[dw + 2];
            acc[Bs][3] += wv * v[dw + 3];
          }
        }
      }
    }
  }

  const int wy = h >> 3, ty = h & 7, wx = w0 >> 3, tx0 = w0 & 7;
  float* op = outw + (size_t)((((b * 16 + wy) * 16 + wx) * 56 + o) * 8) * 64
                   + ty * 8 + tx0;
#pragma unroll
  for (int Bs = 0; Bs < 8; Bs++) {
    float4 r = make_float4(acc[Bs][0], acc[Bs][1], acc[Bs][2], acc[Bs][3]);
    *(float4*)(op + Bs * 64) = r;
  }
}

// ---------------------------------------------------------------------------
// Attention: one block per (b, wy, wx, head) = 2048 blocks, 256 threads.
// Loops 8 depth slices; smem throughout, conflict-free (65-padded rows).
// Fuses the final grouped 1x1x1 conv (2 out channels per attn channel).
// ---------------------------------------------------------------------------
__global__ __launch_bounds__(256) void attn_kernel(
    const float* __restrict__ pcq_w, const float* __restrict__ pcq_b,
    const float* __restrict__ pck_w, const float* __restrict__ pck_b,
    const float* __restrict__ mlp1_w, const float* __restrict__ mlp2_w1,
    const float* __restrict__ mlp2_w2, const float* __restrict__ Wout,
    float* __restrict__ out)
{
  __shared__ float q_s[896], k_s[896], v_s[896];   // [d(14)][tok(64)]
  __shared__ float sim[64 * 65];                   // [i][j], padded
  __shared__ float w1t[64 * 65];                   // w1t[i*65+o] = mlp2_w1[o,i]
  __shared__ float m1[64], w2[64], t1s[64], Sqs[64], Sks[64], red[64];
  __shared__ float pcqw[14], pckw[14], woutc[28];
  __shared__ float theta_s, bq, bk;

  const int tid = threadIdx.x;
  const int bid = blockIdx.x;
  const int head = bid & 3, win = bid >> 2;
  const int b = win >> 8, wy = (win >> 4) & 15, wx = win & 15;

  // per-block constants
  for (int idx = tid; idx < 4096; idx += 256) {
    int o = idx >> 6, i = idx & 63;
    w1t[i * 65 + o] = mlp2_w1[idx];                // idx = o*64+i (coalesced)
  }
  if (tid < 64) { m1[tid] = mlp1_w[tid]; w2[tid] = mlp2_w2[tid]; }
  if (tid < 14) { pcqw[tid] = pcq_w[tid]; pckw[tid] = pck_w[tid]; }
  if (tid < 28) woutc[tid] = Wout[head * 28 + tid];
  if (tid == 0) { bq = pcq_b[0]; bk = pck_b[0]; }

  const size_t wbase = (size_t)((b * 16 + wy) * 16 + wx) * (56 * 8 * 64);
  const float* gq = g_q + wbase + head * 14 * 512;
  const float* gk = g_k + wbase + head * 14 * 512;
  const float* gv = g_v + wbase + head * 14 * 512;

  for (int Bs = 0; Bs < 8; Bs++) {
    __syncthreads();   // protect smem reuse across slices
    for (int idx = tid; idx < 896; idx += 256) {
      int d = idx >> 6, t = idx & 63;
      int ga = d * 512 + Bs * 64 + t;
      q_s[idx] = gq[ga]; k_s[idx] = gk[ga]; v_s[idx] = gv[ga];
    }
    __syncthreads();

    // Sigma projections
    if (tid < 128) {
      int i = tid & 63;
      if (tid < 64) {
        float s = bq;
#pragma unroll
        for (int d = 0; d < 14; d++) s += q_s[d * 64 + i] * pcqw[d];
        Sqs[i] = s;
      } else {
        float s = bk;
#pragma unroll
        for (int d = 0; d < 14; d++) s += k_s[d * 64 + i] * pckw[d];
        Sks[i] = s;
      }
    }

    // sim = q^T k  (each thread: 16 dots of length 14)
    {
      int i = tid & 63, jb = (tid >> 6) * 16;
      float qd[14];
#pragma unroll
      for (int d = 0; d < 14; d++) qd[d] = q_s[d * 64 + i];
#pragma unroll
      for (int jj = 0; jj < 16; jj++) {
        int j = jb + jj;
        float s = 0.f;
#pragma unroll
        for (int d = 0; d < 14; d++) s += qd[d] * k_s[d * 64 + j];
        sim[i * 65 + j] = s;
      }
    }
    __syncthreads();

    // t1 = (sim w/o diag) @ m1
    if (tid < 64) {
      float s = 0.f;
#pragma unroll 8
      for (int j = 0; j < 64; j++) s += sim[tid * 65 + j] * m1[j];
      s -= sim[tid * 65 + tid] * m1[tid];
      t1s[tid] = s;
    }
    __syncthreads();
    // t2 = leaky_relu(t1 @ w1^T), theta = t2 . w2
    if (tid < 64) {
      float s = 0.f;
#pragma unroll 8
      for (int i = 0; i < 64; i++) s += t1s[i] * w1t[i * 65 + tid];
      s = (s > 0.f) ? s : 0.1f * s;
      red[tid] = s * w2[tid];
    }
    __syncthreads();
    if (tid == 0) {
      float s = 0.f;
      for (int i = 0; i < 64; i++) s += red[i];
      theta_s = s;
    }
    __syncthreads();

    // sims = sim * Sq_i * Sk_j ; softmax over j ; mask sims > theta
    if (tid < 64) {
      const int i = tid;
      const float sq = Sqs[i];
      const float th = theta_s;
      float m = -1e30f;
#pragma unroll 8
      for (int j = 0; j < 64; j++) {
        float x = sim[i * 65 + j] * sq * Sks[j];
        sim[i * 65 + j] = x;
        m = fmaxf(m, x);
      }
      float sum = 0.f;
#pragma unroll 8
      for (int j = 0; j < 64; j++) {
        float x = sim[i * 65 + j];
        float e = __expf(x - m);
        sum += e;
        sim[i * 65 + j] = (x > th) ? e : 0.f;
      }
      float r = 1.f / sum;
#pragma unroll 8
      for (int j = 0; j < 64; j++) sim[i * 65 + j] *= r;
    }
    __syncthreads();

    // out = attn @ v^T, fuse 1x1x1 grouped conv, store
    {
      int i = tid & 63, q = tid >> 6;
      float o4[4] = {0.f, 0.f, 0.f, 0.f};
#pragma unroll 8
      for (int j = 0; j < 64; j++) {
        float a = sim[i * 65 + j];
        o4[0] += a * v_s[(q + 0) * 64 + j];
        o4[1] += a * v_s[(q + 4) * 64 + j];
        o4[2] += a * v_s[(q + 8) * 64 + j];
        if (q < 2) o4[3] += a * v_s[(q + 12) * 64 + j];
      }
      const int h = wy * 8 + (i >> 3), w = wx * 8 + (i & 7);
      const size_t sp = (size_t)Bs * 16384 + h * 128 + w;
#pragma unroll
      for (int kk = 0; kk < 4; kk++) {
        int d = q + 4 * kk;
        if (d < 14) {
          int c = head * 14 + d;
          float v0 = o4[kk] * woutc[d * 2 + 0];
          float v1 = o4[kk] * woutc[d * 2 + 1];
          out[(size_t)(b * 112 + 2 * c + 0) * 131072 + sp] = v0;
          out[(size_t)(b * 112 + 2 * c + 1) * 131072 + sp] = v1;
        }
      }
    }
  }
}

extern "C" void kernel_launch(void* const* d_in, const int* in_sizes, int n_in,
                              void* d_out, int out_size) {
  (void)in_sizes; (void)n_in; (void)out_size;
  const float* x      = (const float*)d_in[0];
  const float* last   = (const float*)d_in[1];
  const float* Wq     = (const float*)d_in[2];
  const float* Wk     = (const float*)d_in[3];
  const float* Wv     = (const float*)d_in[4];
  const float* Wout   = (const float*)d_in[5];
  const float* pcq_w  = (const float*)d_in[6];
  const float* pcq_b  = (const float*)d_in[7];
  const float* pck_w  = (const float*)d_in[8];
  const float* pck_b  = (const float*)d_in[9];
  const float* mlp1_w = (const float*)d_in[10];
  const float* mlp2w1 = (const float*)d_in[11];
  const float* mlp2w2 = (const float*)d_in[12];
  float* out = (float*)d_out;

  dim3 gC(1, 16, 112), bC(32, 8);
  conv_win_kernel<<<gC, bC>>>(x,    Wq, 0);
  conv_win_kernel<<<gC, bC>>>(last, Wk, 1);
  conv_win_kernel<<<gC, bC>>>(last, Wv, 2);
  attn_kernel<<<2048, 256>>>(pcq_w, pcq_b, pck_w, pck_b,
                             mlp1_w, mlp2w1, mlp2w2, Wout, out);
}

// round 3
// speedup vs baseline: 1.2101x; 1.2101x over previous
#include <cuda_runtime.h>

// qkv scratch in windowed layout: [b(2)][wy(16)][wx(16)][ch(56)][Bs(8)][tok(64)]
#define NELEM_QKV (2*16*16*56*8*64)
__device__ float g_q[NELEM_QKV];
__device__ float g_k[NELEM_QKV];
__device__ float g_v[NELEM_QKV];

// ---------------------------------------------------------------------------
// All three grouped 3x3x3 convs in ONE launch.
// z < 112            : q conv from x        (idx = z)
// z >= 112, even/odd : k / v conv from last (idx = (z-112)>>1)  -- k,v blocks
//                      for the same channel are adjacent so `last` rows are
//                      fetched from DRAM once and L2-hit the second time.
// Thread: 4 consecutive w outputs for all 8 output depths of one (b,o,h).
// ---------------------------------------------------------------------------
__global__ __launch_bounds__(256) void conv_all_kernel(
    const float* __restrict__ x, const float* __restrict__ last,
    const float* __restrict__ Wq, const float* __restrict__ Wk,
    const float* __restrict__ Wv)
{
  const int z = blockIdx.z;
  int idx, sel;
  if (z < 112) { idx = z; sel = 0; }
  else { int zz = z - 112; idx = zz >> 1; sel = 1 + (zz & 1); }
  const float* in = (sel == 0) ? x : last;
  const float* W3 = (sel == 0) ? Wq : (sel == 1) ? Wk : Wv;
  float* outw     = (sel == 0) ? g_q : (sel == 1) ? g_k : g_v;

  const int b = idx / 56, o = idx % 56;
  const int h = blockIdx.y * 8 + threadIdx.y;
  const int w0 = threadIdx.x * 4;

  __shared__ float ws[54];
  const int tid = threadIdx.y * 32 + threadIdx.x;
  if (tid < 54) ws[tid] = W3[o * 54 + tid];
  __syncthreads();

  float acc[8][4];
#pragma unroll
  for (int i = 0; i < 8; i++) {
    acc[i][0] = 0.f; acc[i][1] = 0.f; acc[i][2] = 0.f; acc[i][3] = 0.f;
  }

#pragma unroll
  for (int ci = 0; ci < 2; ci++) {
    const float* basec = in + (size_t)((b * 112 + o * 2 + ci) * 8) * 16384;
#pragma unroll
    for (int dh = 0; dh < 3; dh++) {
      const int hh = h + dh - 1;
      if (hh < 0 || hh > 127) continue;
      float w9[3][3];
#pragma unroll
      for (int kd = 0; kd < 3; kd++)
#pragma unroll
        for (int dw = 0; dw < 3; dw++)
          w9[kd][dw] = ws[ci * 27 + kd * 9 + dh * 3 + dw];
      const float* rowp = basec + hh * 128 + w0;
#pragma unroll
      for (int d = 0; d < 8; d++) {          // input depth index
        const float* p = rowp + d * 16384;
        float4 m4 = *(const float4*)p;
        float v[6];
        v[0] = (w0 > 0)   ? p[-1] : 0.f;
        v[1] = m4.x; v[2] = m4.y; v[3] = m4.z; v[4] = m4.w;
        v[5] = (w0 < 124) ? p[4]  : 0.f;
#pragma unroll
        for (int kd = 0; kd < 3; kd++) {
          const int Bs = d + 1 - kd;          // output depth fed by this tap
          if (Bs < 0 || Bs > 7) continue;     // compile-time DCE
#pragma unroll
          for (int dw = 0; dw < 3; dw++) {
            const float wv = w9[kd][dw];
            acc[Bs][0] += wv * v[dw + 0];
            acc[Bs][1] += wv * v[dw + 1];
            acc[Bs][2] += wv * v[dw + 2];
            acc[Bs][3] += wv * v[dw + 3];
          }
        }
      }
    }
  }

  const int wy = h >> 3, ty = h & 7, wx = w0 >> 3, tx0 = w0 & 7;
  float* op = outw + (size_t)((((b * 16 + wy) * 16 + wx) * 56 + o) * 8) * 64
                   + ty * 8 + tx0;
#pragma unroll
  for (int Bs = 0; Bs < 8; Bs++) {
    float4 r = make_float4(acc[Bs][0], acc[Bs][1], acc[Bs][2], acc[Bs][3]);
    *(float4*)(op + Bs * 64) = r;
  }
}

// ---------------------------------------------------------------------------
// Attention: one block per (b, wy, wx, head) = 2048 blocks, 256 threads.
// All smem traffic vectorized (LDS.128); all 256 threads active in every
// phase; mlp2_w1 streamed from global (L1-cached, shared by all blocks).
// ---------------------------------------------------------------------------
#define SPAD 68   // sim row stride in floats (16B aligned)

__global__ __launch_bounds__(256) void attn_kernel(
    const float* __restrict__ pcq_w, const float* __restrict__ pcq_b,
    const float* __restrict__ pck_w, const float* __restrict__ pck_b,
    const float* __restrict__ mlp1_w, const float* __restrict__ mlp2_w1,
    const float* __restrict__ mlp2_w2, const float* __restrict__ Wout,
    float* __restrict__ out)
{
  __shared__ __align__(16) float q_s[896], k_s[896], v_s[896]; // [d(14)][tok]
  __shared__ __align__(16) float sim[64 * SPAD];
  __shared__ __align__(16) float m1[64], w2[64], t1s[64];
  __shared__ __align__(16) float Sqs[64], Sks[64], red[64];
  __shared__ float pcqw[14], pckw[14], woutc[28];
  __shared__ float theta_s, bq, bk;

  const int tid = threadIdx.x;
  const int bid = blockIdx.x;
  const int head = bid & 3, win = bid >> 2;
  const int b = win >> 8, wy = (win >> 4) & 15, wx = win & 15;

  if (tid < 64) { m1[tid] = mlp1_w[tid]; w2[tid] = mlp2_w2[tid]; }
  if (tid < 14) { pcqw[tid] = pcq_w[tid]; pckw[tid] = pck_w[tid]; }
  if (tid < 28) woutc[tid] = Wout[head * 28 + tid];
  if (tid == 0) { bq = pcq_b[0]; bk = pck_b[0]; }

  const size_t wbase = (size_t)((b * 16 + wy) * 16 + wx) * (56 * 8 * 64);
  const float4* gq = (const float4*)(g_q + wbase + head * 14 * 512);
  const float4* gk = (const float4*)(g_k + wbase + head * 14 * 512);
  const float4* gv = (const float4*)(g_v + wbase + head * 14 * 512);

  float4* q4 = (float4*)q_s; float4* k4 = (float4*)k_s; float4* v4 = (float4*)v_s;
  float4* sim4 = (float4*)sim;
  const float4* Sks4 = (const float4*)Sks;

  const int irow = tid >> 2, p4 = tid & 3;      // 4 lanes per row mapping

  for (int Bs = 0; Bs < 8; Bs++) {
    __syncthreads();   // protect smem reuse across slices
    // ---- A: load q,k,v slice (float4) ----
    if (tid < 224) {
      int d = tid >> 4, t4 = tid & 15;
      int ga = d * 128 + Bs * 16 + t4;          // float4 index: d*512/4 etc.
      q4[d * 16 + t4] = gq[ga];
      k4[d * 16 + t4] = gk[ga];
      v4[d * 16 + t4] = gv[ga];
    }
    __syncthreads();

    // ---- B: sigma projections (128 threads) ----
    if (tid < 128) {
      int i = tid & 63;
      if (tid < 64) {
        float s = bq;
#pragma unroll
        for (int d = 0; d < 14; d++) s += q_s[d * 64 + i] * pcqw[d];
        Sqs[i] = s;
      } else {
        float s = bk;
#pragma unroll
        for (int d = 0; d < 14; d++) s += k_s[d * 64 + i] * pckw[d];
        Sks[i] = s;
      }
    }

    // ---- C: sim = q^T k, 4x4 register tile per thread ----
    {
      const int it = tid >> 4, jt = tid & 15;
      float a00=0,a01=0,a02=0,a03=0, a10=0,a11=0,a12=0,a13=0;
      float a20=0,a21=0,a22=0,a23=0, a30=0,a31=0,a32=0,a33=0;
#pragma unroll
      for (int d = 0; d < 14; d++) {
        float4 qv = q4[d * 16 + it];
        float4 kv = k4[d * 16 + jt];
        a00 += qv.x*kv.x; a01 += qv.x*kv.y; a02 += qv.x*kv.z; a03 += qv.x*kv.w;
        a10 += qv.y*kv.x; a11 += qv.y*kv.y; a12 += qv.y*kv.z; a13 += qv.y*kv.w;
        a20 += qv.z*kv.x; a21 += qv.z*kv.y; a22 += qv.z*kv.z; a23 += qv.z*kv.w;
        a30 += qv.w*kv.x; a31 += qv.w*kv.y; a32 += qv.w*kv.z; a33 += qv.w*kv.w;
      }
      const int rbase = it * 4, cq = jt;        // float4 col index
      sim4[(rbase+0) * (SPAD/4) + cq] = make_float4(a00,a01,a02,a03);
      sim4[(rbase+1) * (SPAD/4) + cq] = make_float4(a10,a11,a12,a13);
      sim4[(rbase+2) * (SPAD/4) + cq] = make_float4(a20,a21,a22,a23);
      sim4[(rbase+3) * (SPAD/4) + cq] = make_float4(a30,a31,a32,a33);
    }
    __syncthreads();

    // ---- D: t1 = (sim w/o diag) @ m1, 4 lanes/row + shuffle reduce ----
    {
      float s = 0.f;
#pragma unroll
      for (int c = 0; c < 4; c++) {
        int j0 = p4 * 16 + c * 4;
        float4 sv = sim4[irow * (SPAD/4) + p4 * 4 + c];
        s += sv.x * m1[j0] + sv.y * m1[j0+1] + sv.z * m1[j0+2] + sv.w * m1[j0+3];
      }
      if ((irow >> 4) == p4) s -= sim[irow * SPAD + irow] * m1[irow];
      s += __shfl_xor_sync(0xffffffffu, s, 1);
      s += __shfl_xor_sync(0xffffffffu, s, 2);
      if (p4 == 0) t1s[irow] = s;
    }
    __syncthreads();

    // ---- E: t2 = leaky(t1 @ w1^T), theta = t2 . w2 ----
    {
      const float4* w1g = (const float4*)(mlp2_w1 + irow * 64 + p4 * 16);
      float s = 0.f;
#pragma unroll
      for (int c = 0; c < 4; c++) {
        int j0 = p4 * 16 + c * 4;
        float4 wv = __ldg(&w1g[c]);
        s += wv.x * t1s[j0] + wv.y * t1s[j0+1] + wv.z * t1s[j0+2] + wv.w * t1s[j0+3];
      }
      s += __shfl_xor_sync(0xffffffffu, s, 1);
      s += __shfl_xor_sync(0xffffffffu, s, 2);
      if (p4 == 0) {
        s = (s > 0.f) ? s : 0.1f * s;
        red[irow] = s * w2[irow];
      }
    }
    __syncthreads();
    if (tid < 32) {
      float s = red[tid] + red[tid + 32];
#pragma unroll
      for (int off = 16; off > 0; off >>= 1)
        s += __shfl_xor_sync(0xffffffffu, s, off);
      if (tid == 0) theta_s = s;
    }
    __syncthreads();

    // ---- F: sims = sim*Sq_i*Sk_j ; softmax over j ; mask > theta ----
    {
      const float sq = Sqs[irow];
      const float th = theta_s;
      float m = -1e30f;
      float4 xs[4];
#pragma unroll
      for (int c = 0; c < 4; c++) {
        float4 sv = sim4[irow * (SPAD/4) + p4 * 4 + c];
        float4 kv = Sks4[p4 * 4 + c];
        xs[c].x = sv.x * sq * kv.x; xs[c].y = sv.y * sq * kv.y;
        xs[c].z = sv.z * sq * kv.z; xs[c].w = sv.w * sq * kv.w;
        m = fmaxf(m, fmaxf(fmaxf(xs[c].x, xs[c].y), fmaxf(xs[c].z, xs[c].w)));
      }
      m = fmaxf(m, __shfl_xor_sync(0xffffffffu, m, 1));
      m = fmaxf(m, __shfl_xor_sync(0xffffffffu, m, 2));
      float sum = 0.f;
      float4 es[4];
#pragma unroll
      for (int c = 0; c < 4; c++) {
        float4 x = xs[c];
        float4 e;
        e.x = __expf(x.x - m); e.y = __expf(x.y - m);
        e.z = __expf(x.z - m); e.w = __expf(x.w - m);
        sum += e.x + e.y + e.z + e.w;
        es[c].x = (x.x > th) ? e.x : 0.f;
        es[c].y = (x.y > th) ? e.y : 0.f;
        es[c].z = (x.z > th) ? e.z : 0.f;
        es[c].w = (x.w > th) ? e.w : 0.f;
      }
      sum += __shfl_xor_sync(0xffffffffu, sum, 1);
      sum += __shfl_xor_sync(0xffffffffu, sum, 2);
      const float r = 1.f / sum;
#pragma unroll
      for (int c = 0; c < 4; c++) {
        es[c].x *= r; es[c].y *= r; es[c].z *= r; es[c].w *= r;
        sim4[irow * (SPAD/4) + p4 * 4 + c] = es[c];
      }
    }
    __syncthreads();

    // ---- G: out = attn @ v^T, fuse grouped 1x1x1 conv, store ----
    {
      const int i = tid & 63, q = tid >> 6;
      float o0 = 0.f, o1 = 0.f, o2 = 0.f, o3 = 0.f;
#pragma unroll
      for (int jj = 0; jj < 16; jj++) {
        float4 a = sim4[i * (SPAD/4) + jj];
        float4 vA = v4[(q + 0) * 16 + jj];
        float4 vB = v4[(q + 4) * 16 + jj];
        float4 vC = v4[(q + 8) * 16 + jj];
        o0 += a.x*vA.x + a.y*vA.y + a.z*vA.z + a.w*vA.w;
        o1 += a.x*vB.x + a.y*vB.y + a.z*vB.z + a.w*vB.w;
        o2 += a.x*vC.x + a.y*vC.y + a.z*vC.z + a.w*vC.w;
        if (q < 2) {
          float4 vD = v4[(q + 12) * 16 + jj];
          o3 += a.x*vD.x + a.y*vD.y + a.z*vD.z + a.w*vD.w;
        }
      }
      const int h = wy * 8 + (i >> 3), w = wx * 8 + (i & 7);
      const size_t sp = (size_t)Bs * 16384 + h * 128 + w;
      float ov[4] = {o0, o1, o2, o3};
#pragma unroll
      for (int kk = 0; kk < 4; kk++) {
        int d = q + 4 * kk;
        if (d < 14) {
          int c = head * 14 + d;
          out[(size_t)(b * 112 + 2 * c + 0) * 131072 + sp] = ov[kk] * woutc[d * 2 + 0];
          out[(size_t)(b * 112 + 2 * c + 1) * 131072 + sp] = ov[kk] * woutc[d * 2 + 1];
        }
      }
    }
  }
}

extern "C" void kernel_launch(void* const* d_in, const int* in_sizes, int n_in,
                              void* d_out, int out_size) {
  (void)in_sizes; (void)n_in; (void)out_size;
  const float* x      = (const float*)d_in[0];
  const float* last   = (const float*)d_in[1];
  const float* Wq     = (const float*)d_in[2];
  const float* Wk     = (const float*)d_in[3];
  const float* Wv     = (const float*)d_in[4];
  const float* Wout   = (const float*)d_in[5];
  const float* pcq_w  = (const float*)d_in[6];
  const float* pcq_b  = (const float*)d_in[7];
  const float* pck_w  = (const float*)d_in[8];
  const float* pck_b  = (const float*)d_in[9];
  const float* mlp1_w = (const float*)d_in[10];
  const float* mlp2w1 = (const float*)d_in[11];
  const float* mlp2w2 = (const float*)d_in[12];
  float* out = (float*)d_out;

  conv_all_kernel<<<dim3(1, 16, 336), dim3(32, 8)>>>(x, last, Wq, Wk, Wv);
  attn_kernel<<<2048, 256>>>(pcq_w, pcq_b, pck_w, pck_b,
                             mlp1_w, mlp2w1, mlp2w2, Wout, out);
}

// round 4
// speedup vs baseline: 1.3375x; 1.1053x over previous
#include <cuda_runtime.h>

typedef unsigned long long u64;

__device__ __forceinline__ u64 pk2(float a, float b) {
  u64 r; asm("mov.b64 %0, {%1, %2};" : "=l"(r) : "f"(a), "f"(b)); return r;
}
__device__ __forceinline__ void ffma2(u64& d, u64 a, u64 b) {
  asm("fma.rn.f32x2 %0, %1, %2, %0;" : "+l"(d) : "l"(a), "l"(b));
}
__device__ __forceinline__ float2 upk2(u64 v) {
  float2 r; asm("mov.b64 {%0, %1}, %2;" : "=f"(r.x), "=f"(r.y) : "l"(v)); return r;
}

// qkv scratch in windowed layout: [b(2)][wy(16)][wx(16)][ch(56)][Bs(8)][tok(64)]
#define NELEM_QKV (2*16*16*56*8*64)
__device__ float g_q[NELEM_QKV];
__device__ float g_k[NELEM_QKV];
__device__ float g_v[NELEM_QKV];

// ---------------------------------------------------------------------------
// All three grouped 3x3x3 convs, one launch, packed f32x2 FMAs.
// z < 112: q from x.  z >= 112: k/v from last, interleaved so the same `last`
// rows L2-hit for the v pass.
// ---------------------------------------------------------------------------
__global__ __launch_bounds__(256) void conv_all_kernel(
    const float* __restrict__ x, const float* __restrict__ last,
    const float* __restrict__ Wq, const float* __restrict__ Wk,
    const float* __restrict__ Wv)
{
  const int z = blockIdx.z;
  int idx, sel;
  if (z < 112) { idx = z; sel = 0; }
  else { int zz = z - 112; idx = zz >> 1; sel = 1 + (zz & 1); }
  const float* in = (sel == 0) ? x : last;
  const float* W3 = (sel == 0) ? Wq : (sel == 1) ? Wk : Wv;
  float* outw     = (sel == 0) ? g_q : (sel == 1) ? g_k : g_v;

  const int b = idx / 56, o = idx % 56;
  const int h = blockIdx.y * 8 + threadIdx.y;
  const int w0 = threadIdx.x * 4;

  __shared__ float ws[54];
  const int tid = threadIdx.y * 32 + threadIdx.x;
  if (tid < 54) ws[tid] = W3[o * 54 + tid];
  __syncthreads();

  u64 acc2[8][2];
#pragma unroll
  for (int i = 0; i < 8; i++) { acc2[i][0] = 0ull; acc2[i][1] = 0ull; }

#pragma unroll
  for (int ci = 0; ci < 2; ci++) {
    const float* basec = in + (size_t)((b * 112 + o * 2 + ci) * 8) * 16384;
#pragma unroll
    for (int dh = 0; dh < 3; dh++) {
      const int hh = h + dh - 1;
      if (hh < 0 || hh > 127) continue;
      u64 w2p[3][3];
#pragma unroll
      for (int kd = 0; kd < 3; kd++)
#pragma unroll
        for (int dw = 0; dw < 3; dw++) {
          float wv = ws[ci * 27 + kd * 9 + dh * 3 + dw];
          w2p[kd][dw] = pk2(wv, wv);
        }
      const float* rowp = basec + hh * 128 + w0;
#pragma unroll
      for (int d = 0; d < 8; d++) {          // input depth index
        const float* p = rowp + d * 16384;
        float4 m4 = *(const float4*)p;
        float v[6];
        v[0] = (w0 > 0)   ? p[-1] : 0.f;
        v[1] = m4.x; v[2] = m4.y; v[3] = m4.z; v[4] = m4.w;
        v[5] = (w0 < 124) ? p[4]  : 0.f;
        u64 pv[5];
#pragma unroll
        for (int k = 0; k < 5; k++) pv[k] = pk2(v[k], v[k + 1]);
#pragma unroll
        for (int kd = 0; kd < 3; kd++) {
          const int Bs = d + 1 - kd;          // output depth fed by this tap
          if (Bs < 0 || Bs > 7) continue;     // compile-time DCE
#pragma unroll
          for (int dw = 0; dw < 3; dw++) {
            ffma2(acc2[Bs][0], w2p[kd][dw], pv[dw]);
            ffma2(acc2[Bs][1], w2p[kd][dw], pv[dw + 2]);
          }
        }
      }
    }
  }

  const int wy = h >> 3, ty = h & 7, wx = w0 >> 3, tx0 = w0 & 7;
  float* op = outw + (size_t)((((b * 16 + wy) * 16 + wx) * 56 + o) * 8) * 64
                   + ty * 8 + tx0;
#pragma unroll
  for (int Bs = 0; Bs < 8; Bs++) {
    float2 lo = upk2(acc2[Bs][0]), hi = upk2(acc2[Bs][1]);
    *(float4*)(op + Bs * 64) = make_float4(lo.x, lo.y, hi.x, hi.y);
  }
}

// ---------------------------------------------------------------------------
// Attention. Quad ownership (irow = tid>>2, p4 = tid&3) for softmax+out GEMM,
// fully register-resident between sim read and global store. v stored with
// quarter-permuted layout so quad v-loads are 64B-contiguous.
// ---------------------------------------------------------------------------
#define SPAD 68   // sim row stride in floats

__global__ __launch_bounds__(256) void attn_kernel(
    const float* __restrict__ pcq_w, const float* __restrict__ pcq_b,
    const float* __restrict__ pck_w, const float* __restrict__ pck_b,
    const float* __restrict__ mlp1_w, const float* __restrict__ mlp2_w1,
    const float* __restrict__ mlp2_w2, const float* __restrict__ Wout,
    float* __restrict__ out)
{
  __shared__ __align__(16) float q_s[896], k_s[896], v_s[896];
  __shared__ __align__(16) float sim[64 * SPAD];
  __shared__ __align__(16) float m1[64], w2[64], t1s[64];
  __shared__ __align__(16) float Sqs[64], Sks[64], red[64];
  __shared__ float pcqw[14], pckw[14], woutc[28];
  __shared__ float theta_s, bq, bk;

  const int tid = threadIdx.x;
  const int bid = blockIdx.x;
  const int head = bid & 3, win = bid >> 2;
  const int b = win >> 8, wy = (win >> 4) & 15, wx = win & 15;

  if (tid < 64) { m1[tid] = mlp1_w[tid]; w2[tid] = mlp2_w2[tid]; }
  if (tid < 14) { pcqw[tid] = pcq_w[tid]; pckw[tid] = pck_w[tid]; }
  if (tid < 28) woutc[tid] = Wout[head * 28 + tid];
  if (tid == 0) { bq = pcq_b[0]; bk = pck_b[0]; }

  const size_t wbase = (size_t)((b * 16 + wy) * 16 + wx) * (56 * 8 * 64);
  const float4* gq = (const float4*)(g_q + wbase + head * 14 * 512);
  const float4* gk = (const float4*)(g_k + wbase + head * 14 * 512);
  const float4* gv = (const float4*)(g_v + wbase + head * 14 * 512);

  float4* q4 = (float4*)q_s; float4* k4 = (float4*)k_s; float4* v4 = (float4*)v_s;
  float4* sim4 = (float4*)sim;
  const float4* Sks4 = (const float4*)Sks;
  const float4* m14  = (const float4*)m1;

  const int irow = tid >> 2, p4 = tid & 3;     // quad ownership
  const int it = tid >> 4, jt = tid & 15;      // 4x4 tile ownership

  const int hh = wy * 8 + (irow >> 3), ww = wx * 8 + (irow & 7);

  for (int Bs = 0; Bs < 8; Bs++) {
    __syncthreads();   // protect smem reuse across slices
    // ---- A: load q,k,v slice; v quarter-permuted ----
    if (tid < 224) {
      int d = tid >> 4, t4 = tid & 15;
      int ga = d * 128 + Bs * 16 + t4;
      q4[d * 16 + t4] = gq[ga];
      k4[d * 16 + t4] = gk[ga];
      v4[d * 16 + (t4 & 3) * 4 + (t4 >> 2)] = gv[ga];
    }
    __syncthreads();

    // ---- B: sigma projections (Sks stored pre-permuted) ----
    if (tid < 128) {
      int i = tid & 63;
      if (tid < 64) {
        float s = bq;
#pragma unroll
        for (int d = 0; d < 14; d++) s += q_s[d * 64 + i] * pcqw[d];
        Sqs[i] = s;
      } else {
        float s = bk;
#pragma unroll
        for (int d = 0; d < 14; d++) s += k_s[d * 64 + i] * pckw[d];
        // i = pp*16 + cc*4 + ee  ->  store at (cc*4+pp)*4 + ee
        Sks[(((i >> 2) & 3) * 4 + (i >> 4)) * 4 + (i & 3)] = s;
      }
    }

    // ---- C: sim = q^T k (4x4 tiles) + fold t1 partials via shfl ----
    {
      float a00=0,a01=0,a02=0,a03=0, a10=0,a11=0,a12=0,a13=0;
      float a20=0,a21=0,a22=0,a23=0, a30=0,a31=0,a32=0,a33=0;
#pragma unroll
      for (int d = 0; d < 14; d++) {
        float4 qv = q4[d * 16 + it];
        float4 kv = k4[d * 16 + jt];
        a00 += qv.x*kv.x; a01 += qv.x*kv.y; a02 += qv.x*kv.z; a03 += qv.x*kv.w;
        a10 += qv.y*kv.x; a11 += qv.y*kv.y; a12 += qv.y*kv.z; a13 += qv.y*kv.w;
        a20 += qv.z*kv.x; a21 += qv.z*kv.y; a22 += qv.z*kv.z; a23 += qv.z*kv.w;
        a30 += qv.w*kv.x; a31 += qv.w*kv.y; a32 += qv.w*kv.z; a33 += qv.w*kv.w;
      }
      const int rbase = it * 4;
      sim4[(rbase+0) * (SPAD/4) + jt] = make_float4(a00,a01,a02,a03);
      sim4[(rbase+1) * (SPAD/4) + jt] = make_float4(a10,a11,a12,a13);
      sim4[(rbase+2) * (SPAD/4) + jt] = make_float4(a20,a21,a22,a23);
      sim4[(rbase+3) * (SPAD/4) + jt] = make_float4(a30,a31,a32,a33);

      // t1 partial: dot of my 4 columns with m1, minus diagonal when it==jt
      float4 mv = m14[jt];
      float pr0 = a00*mv.x + a01*mv.y + a02*mv.z + a03*mv.w;
      float pr1 = a10*mv.x + a11*mv.y + a12*mv.z + a13*mv.w;
      float pr2 = a20*mv.x + a21*mv.y + a22*mv.z + a23*mv.w;
      float pr3 = a30*mv.x + a31*mv.y + a32*mv.z + a33*mv.w;
      if (it == jt) {
        pr0 -= a00 * mv.x; pr1 -= a11 * mv.y;
        pr2 -= a22 * mv.z; pr3 -= a33 * mv.w;
      }
#pragma unroll
      for (int off = 1; off < 16; off <<= 1) {
        pr0 += __shfl_xor_sync(0xffffffffu, pr0, off);
        pr1 += __shfl_xor_sync(0xffffffffu, pr1, off);
        pr2 += __shfl_xor_sync(0xffffffffu, pr2, off);
        pr3 += __shfl_xor_sync(0xffffffffu, pr3, off);
      }
      if (jt == 0) {
        t1s[rbase + 0] = pr0; t1s[rbase + 1] = pr1;
        t1s[rbase + 2] = pr2; t1s[rbase + 3] = pr3;
      }
    }
    __syncthreads();

    // ---- E: t2 = leaky(t1 @ w1^T), theta = t2 . w2 ----
    {
      const float4* w1g = (const float4*)(mlp2_w1 + irow * 64 + p4 * 16);
      float s = 0.f;
#pragma unroll
      for (int c = 0; c < 4; c++) {
        int j0 = p4 * 16 + c * 4;
        float4 wv = __ldg(&w1g[c]);
        s += wv.x * t1s[j0] + wv.y * t1s[j0+1] + wv.z * t1s[j0+2] + wv.w * t1s[j0+3];
      }
      s += __shfl_xor_sync(0xffffffffu, s, 1);
      s += __shfl_xor_sync(0xffffffffu, s, 2);
      if (p4 == 0) {
        s = (s > 0.f) ? s : 0.1f * s;
        red[irow] = s * w2[irow];
      }
    }
    __syncthreads();
    if (tid < 32) {
      float s = red[tid] + red[tid + 32];
#pragma unroll
      for (int off = 16; off > 0; off >>= 1)
        s += __shfl_xor_sync(0xffffffffu, s, off);
      if (tid == 0) theta_s = s;
    }
    __syncthreads();

    // ---- FG fused: scale, softmax, mask, out-GEMM, store ----
    {
      const float sq = Sqs[irow];
      const float th = theta_s;
      float a[16];
      float m = -1e30f;
#pragma unroll
      for (int c = 0; c < 4; c++) {
        float4 sv = sim4[irow * (SPAD/4) + p4 * 4 + c];
        float4 kv = Sks4[c * 4 + p4];          // permuted: holds Sk[p4*16+c*4..]
        a[c*4+0] = sv.x * sq * kv.x; a[c*4+1] = sv.y * sq * kv.y;
        a[c*4+2] = sv.z * sq * kv.z; a[c*4+3] = sv.w * sq * kv.w;
        m = fmaxf(m, fmaxf(fmaxf(a[c*4+0], a[c*4+1]), fmaxf(a[c*4+2], a[c*4+3])));
      }
      m = fmaxf(m, __shfl_xor_sync(0xffffffffu, m, 1));
      m = fmaxf(m, __shfl_xor_sync(0xffffffffu, m, 2));
      float sum = 0.f;
#pragma unroll
      for (int e = 0; e < 16; e++) {
        float xv = a[e];
        float ev = __expf(xv - m);
        sum += ev;
        a[e] = (xv > th) ? ev : 0.f;
      }
      sum += __shfl_xor_sync(0xffffffffu, sum, 1);
      sum += __shfl_xor_sync(0xffffffffu, sum, 2);
      const float r = 1.f / sum;
#pragma unroll
      for (int e = 0; e < 16; e++) a[e] *= r;

      const size_t sp = (size_t)Bs * 16384 + hh * 128 + ww;
      const size_t cb = (size_t)(b * 112 + head * 28) * 131072 + sp;
#pragma unroll
      for (int half = 0; half < 2; half++) {
        float oacc[7] = {0.f,0.f,0.f,0.f,0.f,0.f,0.f};
#pragma unroll
        for (int dd = 0; dd < 7; dd++) {
          const int d = half * 7 + dd;
#pragma unroll
          for (int c = 0; c < 4; c++) {
            float4 vv = v4[d * 16 + c * 4 + p4];   // permuted: v[d][p4*16+c*4..]
            oacc[dd] += a[c*4+0]*vv.x + a[c*4+1]*vv.y
                      + a[c*4+2]*vv.z + a[c*4+3]*vv.w;
          }
        }
#pragma unroll
        for (int dd = 0; dd < 7; dd++) {
          float s = oacc[dd];
          s += __shfl_xor_sync(0xffffffffu, s, 1);
          s += __shfl_xor_sync(0xffffffffu, s, 2);
          oacc[dd] = s;
        }
#pragma unroll
        for (int k = 0; k < 2; k++) {
          const int dd = p4 + 4 * k;
          if (dd < 7) {
            const int d = half * 7 + dd;
            out[cb + (size_t)(2 * d)     * 131072] = oacc[dd] * woutc[d * 2 + 0];
            out[cb + (size_t)(2 * d + 1) * 131072] = oacc[dd] * woutc[d * 2 + 1];
          }
        }
      }
    }
  }
}

extern "C" void kernel_launch(void* const* d_in, const int* in_sizes, int n_in,
                              void* d_out, int out_size) {
  (void)in_sizes; (void)n_in; (void)out_size;
  const float* x      = (const float*)d_in[0];
  const float* last   = (const float*)d_in[1];
  const float* Wq     = (const float*)d_in[2];
  const float* Wk     = (const float*)d_in[3];
  const float* Wv     = (const float*)d_in[4];
  const float* Wout   = (const float*)d_in[5];
  const float* pcq_w  = (const float*)d_in[6];
  const float* pcq_b  = (const float*)d_in[7];
  const float* pck_w  = (const float*)d_in[8];
  const float* pck_b  = (const float*)d_in[9];
  const float* mlp1_w = (const float*)d_in[10];
  const float* mlp2w1 = (const float*)d_in[11];
  const float* mlp2w2 = (const float*)d_in[12];
  float* out = (float*)d_out;

  conv_all_kernel<<<dim3(1, 16, 336), dim3(32, 8)>>>(x, last, Wq, Wk, Wv);
  attn_kernel<<<2048, 256>>>(pcq_w, pcq_b, pck_w, pck_b,
                             mlp1_w, mlp2w1, mlp2w2, Wout, out);
}